// round 16
// baseline (speedup 1.0000x reference)
#include <cuda_runtime.h>
#include <cuda_fp16.h>
#include <cstdint>
#include <math.h>

// Problem constants
#define HID   4096
#define NHEAD 32
#define HDIM  128
#define BATCH 2
#define SEQ   1024
#define MTOK  2048
#define BHTOT 64
#define QSCALE 0.08838834764831845f   // 1/sqrt(128)

// -------- scratch (__device__ globals; no allocation allowed) --------
__device__ __half g_xn [MTOK * HID];            // fp16 layernorm output
__device__ __half g_q  [BHTOT * SEQ * HDIM];    // [bh][s][d], pre-scaled
__device__ __half g_k  [BHTOT * SEQ * HDIM];    // [bh][s][d]
__device__ __half g_v  [BHTOT * SEQ * HDIM];    // [bh][d][s], TRANSPOSED
__device__ __half g_w  [67108864];              // qkv_w^T (50331648) + ow^T (16777216)
__device__ __half g_ctx[MTOK * HID];            // [b*s][h*d]

// -------- low-level helpers --------
__device__ __forceinline__ uint32_t sa(const void* p) {
    return (uint32_t)__cvta_generic_to_shared(p);
}
__device__ __forceinline__ void cp16(uint32_t s, const void* g) {
    asm volatile("cp.async.cg.shared.global [%0], [%1], 16;\n" :: "r"(s), "l"(g));
}
__device__ __forceinline__ void cp_commit() {
    asm volatile("cp.async.commit_group;\n");
}
template<int N>
__device__ __forceinline__ void cp_wait() {
    asm volatile("cp.async.wait_group %0;\n" :: "n"(N));
}
__device__ __forceinline__ void ldsm4(uint32_t r[4], uint32_t a) {
    asm volatile("ldmatrix.sync.aligned.m8n8.x4.shared.b16 {%0,%1,%2,%3}, [%4];"
        : "=r"(r[0]), "=r"(r[1]), "=r"(r[2]), "=r"(r[3]) : "r"(a));
}
// fp16 mma, fp32 accumulate: D(16x8) += A(16x16) @ B(16x8)
__device__ __forceinline__ void mma16(float c[4], const uint32_t a[4],
                                      uint32_t b0, uint32_t b1) {
    asm volatile(
        "mma.sync.aligned.m16n8k16.row.col.f32.f16.f16.f32 "
        "{%0,%1,%2,%3}, {%4,%5,%6,%7}, {%8,%9}, {%0,%1,%2,%3};"
        : "+f"(c[0]), "+f"(c[1]), "+f"(c[2]), "+f"(c[3])
        : "r"(a[0]), "r"(a[1]), "r"(a[2]), "r"(a[3]), "r"(b0), "r"(b1));
}

__device__ __forceinline__ float block_sum(float v) {
    __shared__ float sh[8];
    __syncthreads();
    #pragma unroll
    for (int o = 16; o; o >>= 1) v += __shfl_xor_sync(0xffffffffu, v, o);
    if ((threadIdx.x & 31) == 0) sh[threadIdx.x >> 5] = v;
    __syncthreads();
    v = sh[0];
    #pragma unroll
    for (int i = 1; i < 8; i++) v += sh[i];
    return v;
}

// -------- weight prep: transpose [R][C] -> [C][R], fp32 -> fp16 --------
__global__ void transpose_h(const float* __restrict__ in, __half* __restrict__ out,
                            int R, int C) {
    __shared__ float t[32][33];
    const int tx = threadIdx.x & 31, ty = threadIdx.x >> 5;
    const int c0 = blockIdx.x * 32, r0 = blockIdx.y * 32;
    #pragma unroll
    for (int i = 0; i < 4; i++)
        t[ty + i * 8][tx] = in[(size_t)(r0 + ty + i * 8) * C + c0 + tx];
    __syncthreads();
    #pragma unroll
    for (int i = 0; i < 4; i++)
        out[(size_t)(c0 + ty + i * 8) * R + r0 + tx] = __float2half_rn(t[tx][ty + i * 8]);
}

// -------- layernorm (fp16 output) --------
__global__ void ln_kernel(const float* __restrict__ x, const float* __restrict__ w,
                          const float* __restrict__ bb, __half* __restrict__ o) {
    size_t base = (size_t)blockIdx.x * HID;
    float4 vx[4];
    float s = 0.f, s2 = 0.f;
    #pragma unroll
    for (int i = 0; i < 4; i++) {
        vx[i] = *(const float4*)(x + base + (size_t)(threadIdx.x + i * 256) * 4);
        s  += vx[i].x + vx[i].y + vx[i].z + vx[i].w;
        s2 += vx[i].x * vx[i].x + vx[i].y * vx[i].y + vx[i].z * vx[i].z + vx[i].w * vx[i].w;
    }
    s  = block_sum(s);
    s2 = block_sum(s2);
    float mu  = s * (1.f / HID);
    float var = s2 * (1.f / HID) - mu * mu;
    float rs  = rsqrtf(var + 1e-5f);
    #pragma unroll
    for (int i = 0; i < 4; i++) {
        int c = (threadIdx.x + i * 256) * 4;
        float4 wv = *(const float4*)(w + c);
        float4 bv = *(const float4*)(bb + c);
        *(__half2*)(o + base + c)     = __floats2half2_rn((vx[i].x - mu) * rs * wv.x + bv.x,
                                                          (vx[i].y - mu) * rs * wv.y + bv.y);
        *(__half2*)(o + base + c + 2) = __floats2half2_rn((vx[i].z - mu) * rs * wv.z + bv.z,
                                                          (vx[i].w - mu) * rs * wv.w + bv.w);
    }
}

// -------- fp16 GEMM: C[M,N] = A[M,K] @ B[N,K]^T, 128x128x64, 256 thr, 2x4 warps --------
// R12-proven mainloop: 3-stage cp.async (wait_group 1), single barrier per slice,
// 2 CTAs/SM. MODE 0 v-tiles staged through smem for coalesced 16B stores.
// MODE 0: QKV epilogue (+bias, scatter q/k/v; q scaled; v transposed)
// MODE 3: plain fp32 store
#define GROW 72              // halves per smem row
#define GSTG 36864           // bytes per stage (A+B)

template<int MODE>
__device__ __forceinline__ void epi(int m, int n, float val, int N,
                                    const float* __restrict__ bias,
                                    float* __restrict__ out, __half* __restrict__ oq,
                                    __half* __restrict__ ok_) {
    if (MODE == 0) {
        val += bias[n];
        int which = n >> 12, nn = n & 4095;
        int h = nn >> 7, d = nn & 127, b = m >> 10, s = m & 1023;
        int bh = b * NHEAD + h;
        if (which == 0)      oq [((size_t)bh * 1024 + s) * 128 + d] = __float2half_rn(val * QSCALE);
        else                 ok_[((size_t)bh * 1024 + s) * 128 + d] = __float2half_rn(val);
    } else {
        out[(size_t)m * N + n] = val;
    }
}

template<int MODE>
__global__ void __launch_bounds__(256, 2) gemm_k(
    const __half* __restrict__ A, const __half* __restrict__ B, float* __restrict__ out,
    int N, int K, const float* __restrict__ bias,
    __half* __restrict__ oq, __half* __restrict__ ok_, __half* __restrict__ ov) {
    extern __shared__ __align__(16) char sm[];
    const int tid = threadIdx.x, lane = tid & 31, w = tid >> 5;
    const int wm = w & 1, wn = w >> 1, g = lane >> 2, qt = lane & 3;
    const int m0 = blockIdx.x * 128, n0 = blockIdx.y * 128;   // M fast axis
    const int KT = K / 64;
    const uint32_t smb = sa(sm);

    float acc[4][4][4];
    #pragma unroll
    for (int a = 0; a < 4; a++)
        #pragma unroll
        for (int b = 0; b < 4; b++)
            #pragma unroll
            for (int c = 0; c < 4; c++) acc[a][b][c] = 0.f;

    auto issue = [&](int kt, int st) {
        const uint32_t sA = smb + (uint32_t)st * GSTG;
        const uint32_t sB = sA + 128u * 144u;
        const int k0 = kt * 64;
        #pragma unroll
        for (int i = 0; i < 4; i++) {     // A: 128 rows x 8 chunks of 8 halves
            int id = tid + i * 256;
            int r = id >> 3, c = id & 7;
            cp16(sA + (uint32_t)(r * 144 + c * 16), A + (size_t)(m0 + r) * K + k0 + c * 8);
        }
        #pragma unroll
        for (int i = 0; i < 4; i++) {
            int id = tid + i * 256;
            int r = id >> 3, c = id & 7;
            cp16(sB + (uint32_t)(r * 144 + c * 16), B + (size_t)(n0 + r) * K + k0 + c * 8);
        }
    };

    issue(0, 0); cp_commit();
    issue(1, 1); cp_commit();

    // fragment lane addressing (halves)
    const int arow = wm * 64 + (lane & 7) + (lane & 8);   // + im*16
    const int acol = (lane >> 4) * 8;                     // + kb
    const int brow = (lane & 7) + (lane >> 4) * 8;        // + wn*32 + p*16
    const int bcol = ((lane >> 3) & 1) * 8;               // + kb

    int st_r = 0, st_w = 2;
    for (int kt = 0; kt < KT; kt++) {
        cp_wait<1>();
        __syncthreads();               // single barrier per slice
        if (kt + 2 < KT) issue(kt + 2, st_w);
        cp_commit();                   // commit every iter: group count exact
        if (++st_w == 3) st_w = 0;
        const uint32_t sA = smb + (uint32_t)st_r * GSTG;
        const uint32_t sB = sA + 128u * 144u;
        if (++st_r == 3) st_r = 0;
        #pragma unroll
        for (int ks = 0; ks < 4; ks++) {            // four k16 steps per 64-slice
            const int kb = ks * 16;
            uint32_t af[4][4], bf[2][4];
            #pragma unroll
            for (int im = 0; im < 4; im++)
                ldsm4(af[im], sA + (uint32_t)((arow + im * 16) * GROW + kb + acol) * 2u);
            #pragma unroll
            for (int p = 0; p < 2; p++)
                ldsm4(bf[p], sB + (uint32_t)((wn * 32 + p * 16 + brow) * GROW + kb + bcol) * 2u);
            #pragma unroll
            for (int im = 0; im < 4; im++)
                #pragma unroll
                for (int jn = 0; jn < 4; jn++)
                    mma16(acc[im][jn], af[im], bf[jn >> 1][(jn & 1) * 2],
                          bf[jn >> 1][(jn & 1) * 2 + 1]);
        }
    }

    if (MODE == 0 && n0 >= 8192) {
        // v-tile: stage through smem, then coalesced [d][s] stores.
        __syncthreads();               // stage buffers free
        __half* vs = (__half*)sm;      // [128][136] halves
        #pragma unroll
        for (int im = 0; im < 4; im++) {
            int ml = wm * 64 + im * 16 + g;
            #pragma unroll
            for (int jn = 0; jn < 4; jn++) {
                int nl = wn * 32 + jn * 8 + 2 * qt;
                vs[nl * 136 + ml]           = __float2half_rn(acc[im][jn][0] + bias[n0 + nl]);
                vs[(nl + 1) * 136 + ml]     = __float2half_rn(acc[im][jn][1] + bias[n0 + nl + 1]);
                vs[nl * 136 + ml + 8]       = __float2half_rn(acc[im][jn][2] + bias[n0 + nl]);
                vs[(nl + 1) * 136 + ml + 8] = __float2half_rn(acc[im][jn][3] + bias[n0 + nl + 1]);
            }
        }
        __syncthreads();
        const int b = m0 >> 10, h = (n0 & 4095) >> 7;
        const int bh = b * NHEAD + h, s0 = m0 & 1023;
        #pragma unroll
        for (int i = 0; i < 8; i++) {    // 128 rows x 16 chunks of 16B
            int u = tid + i * 256;
            int r = u >> 4, c = u & 15;
            *(uint4*)(ov + (size_t)(bh * 128 + r) * 1024 + s0 + c * 8) =
                *(uint4*)(vs + r * 136 + c * 8);
        }
    } else {
        #pragma unroll
        for (int im = 0; im < 4; im++) {
            int mr = m0 + wm * 64 + im * 16 + g;
            #pragma unroll
            for (int jn = 0; jn < 4; jn++) {
                int nc = n0 + wn * 32 + jn * 8 + 2 * qt;
                epi<MODE>(mr,     nc,     acc[im][jn][0], N, bias, out, oq, ok_);
                epi<MODE>(mr,     nc + 1, acc[im][jn][1], N, bias, out, oq, ok_);
                epi<MODE>(mr + 8, nc,     acc[im][jn][2], N, bias, out, oq, ok_);
                epi<MODE>(mr + 8, nc + 1, acc[im][jn][3], N, bias, out, oq, ok_);
            }
        }
    }
}

// -------- fp16 flash attention: P in regs, KV double-buffered, 1 barrier/j,
// software-pipelined LDSM->MMA (ping-pong B fragments), heavy CTAs first --------
// per CTA one (bh, 128-row q block); 8 warps x 16 rows.
// smem: K0,K1,V0,V1 (4 x 34816B) + mask (4KB) = 143360B, occ 1.
#define FROW 136
#define FTILE 34816
#define MOFF  (4 * FTILE)

__global__ void __launch_bounds__(256, 1) flash_k(
    const __half* __restrict__ q, const __half* __restrict__ k, const __half* __restrict__ v,
    const float* __restrict__ mask, __half* __restrict__ ctx) {
    extern __shared__ __align__(16) char sm[];
    const int tid = threadIdx.x, lane = tid & 31, w = tid >> 5;
    const int g = lane >> 2, qt = lane & 3;
    const int qb = (int)(gridDim.x - 1) - (int)blockIdx.x;   // heavy CTAs first
    const int bh = blockIdx.y, b = bh >> 5, h = bh & 31;
    const size_t hoff = (size_t)bh * 131072;
    const uint32_t smb = sa(sm);
    float* smf = (float*)(sm + MOFF);

    const int arow = w * 16 + (lane & 7) + (lane & 8);
    const int acol = (lane >> 4) * 8;
    const int brow = (lane & 7) + (lane >> 4) * 8;
    const int bcol = ((lane >> 3) & 1) * 8;

    auto issue_KV = [&](int j, int buf) {
        const uint32_t sK = smb + (uint32_t)buf * FTILE;
        const uint32_t sV = smb + (uint32_t)(2 + buf) * FTILE;
        #pragma unroll
        for (int i = 0; i < 8; i++) {
            int id = tid + i * 256;
            int r = id >> 4, c = id & 15;
            cp16(sK + (uint32_t)(r * 272 + c * 16), k + hoff + (size_t)(j * 128 + r) * 128 + c * 8);
        }
        #pragma unroll
        for (int i = 0; i < 8; i++) {
            int id = tid + i * 256;
            int r = id >> 4, c = id & 15;
            cp16(sV + (uint32_t)(r * 272 + c * 16), v + hoff + (size_t)r * 1024 + j * 128 + c * 8);
        }
    };

    // mask row -> smem (1024 floats)
    *((float4*)smf + tid) = *((const float4*)(mask + b * 1024) + tid);

    // stage Q through K-buffer 0, pull fragments into registers
    {
        const uint32_t sK0 = smb;
        #pragma unroll
        for (int i = 0; i < 8; i++) {
            int id = tid + i * 256;
            int r = id >> 4, c = id & 15;
            cp16(sK0 + (uint32_t)(r * 272 + c * 16), q + hoff + (size_t)(qb * 128 + r) * 128 + c * 8);
        }
        cp_commit(); cp_wait<0>();
    }
    __syncthreads();
    uint32_t qf[8][4];
    #pragma unroll
    for (int kf = 0; kf < 8; kf++)
        ldsm4(qf[kf], smb + (uint32_t)(arow * FROW + kf * 16 + acol) * 2u);
    __syncthreads();           // qf reads done before KV(0) overwrites buffer 0

    issue_KV(0, 0); cp_commit();

    float ctxa[16][4];
    #pragma unroll
    for (int i = 0; i < 16; i++) { ctxa[i][0] = ctxa[i][1] = ctxa[i][2] = ctxa[i][3] = 0.f; }
    float m1 = -1e30f, m2 = -1e30f, l1 = 0.f, l2 = 0.f;
    const int rl1 = w * 16 + g, rl2 = rl1 + 8;

    for (int j = 0; j <= qb; j++) {
        const int buf = j & 1;
        const uint32_t sK = smb + (uint32_t)buf * FTILE;
        const uint32_t sV = smb + (uint32_t)(2 + buf) * FTILE;
        cp_wait<0>();
        __syncthreads();       // KV(j) visible; all warps past PV(j-1)
        if (j < qb) { issue_KV(j + 1, buf ^ 1); cp_commit(); }

        // S = Q @ K^T — flattened (ks,p) loop, ping-pong B fragments:
        // LDSM(i+1) issued before the MMAs of i -> latency overlapped.
        float sacc[16][4];
        #pragma unroll
        for (int i = 0; i < 16; i++) { sacc[i][0] = sacc[i][1] = sacc[i][2] = sacc[i][3] = 0.f; }
        {
            uint32_t bb[2][4];
            ldsm4(bb[0], sK + (uint32_t)(brow * FROW + bcol) * 2u);
            #pragma unroll
            for (int i = 0; i < 64; i++) {
                const int ks = i >> 3, p = i & 7, cur = i & 1;
                if (i < 63) {
                    const int nks = (i + 1) >> 3, np = (i + 1) & 7;
                    ldsm4(bb[cur ^ 1],
                          sK + (uint32_t)((np * 16 + brow) * FROW + nks * 16 + bcol) * 2u);
                }
                mma16(sacc[2 * p],     qf[ks], bb[cur][0], bb[cur][1]);
                mma16(sacc[2 * p + 1], qf[ks], bb[cur][2], bb[cur][3]);
            }
        }

        // online softmax (row stats warp-local; lanes 4g..4g+3 share rows)
        const bool diag = (j == qb);
        float mx1 = -1e30f, mx2 = -1e30f;
        #pragma unroll
        for (int nf = 0; nf < 16; nf++) {
            int c0 = nf * 8 + 2 * qt, cg = j * 128 + c0;
            float mk0 = smf[cg], mk1 = smf[cg + 1];
            float s0 = sacc[nf][0] + mk0, s1 = sacc[nf][1] + mk1;
            float s2 = sacc[nf][2] + mk0, s3 = sacc[nf][3] + mk1;
            if (diag) {
                if (c0     > rl1) s0 = -1e30f;
                if (c0 + 1 > rl1) s1 = -1e30f;
                if (c0     > rl2) s2 = -1e30f;
                if (c0 + 1 > rl2) s3 = -1e30f;
            }
            sacc[nf][0] = s0; sacc[nf][1] = s1; sacc[nf][2] = s2; sacc[nf][3] = s3;
            mx1 = fmaxf(mx1, fmaxf(s0, s1));
            mx2 = fmaxf(mx2, fmaxf(s2, s3));
        }
        #pragma unroll
        for (int o = 1; o < 4; o <<= 1) {
            mx1 = fmaxf(mx1, __shfl_xor_sync(0xffffffffu, mx1, o));
            mx2 = fmaxf(mx2, __shfl_xor_sync(0xffffffffu, mx2, o));
        }
        float mn1 = fmaxf(m1, mx1), mn2 = fmaxf(m2, mx2);
        float sc1 = __expf(m1 - mn1), sc2 = __expf(m2 - mn2);
        float su1 = 0.f, su2 = 0.f;
        uint32_t pA[16], pB[16];       // P as mma A-fragments (rows g / g+8)
        #pragma unroll
        for (int nf = 0; nf < 16; nf++) {
            float p0 = __expf(sacc[nf][0] - mn1), p1 = __expf(sacc[nf][1] - mn1);
            float p2 = __expf(sacc[nf][2] - mn2), p3 = __expf(sacc[nf][3] - mn2);
            su1 += p0 + p1;
            su2 += p2 + p3;
            __half2 h01 = __floats2half2_rn(p0, p1);
            __half2 h23 = __floats2half2_rn(p2, p3);
            pA[nf] = *reinterpret_cast<uint32_t*>(&h01);
            pB[nf] = *reinterpret_cast<uint32_t*>(&h23);
        }
        #pragma unroll
        for (int o = 1; o < 4; o <<= 1) {
            su1 += __shfl_xor_sync(0xffffffffu, su1, o);
            su2 += __shfl_xor_sync(0xffffffffu, su2, o);
        }
        l1 = l1 * sc1 + su1;
        l2 = l2 * sc2 + su2;
        m1 = mn1; m2 = mn2;
        #pragma unroll
        for (int nf = 0; nf < 16; nf++) {
            ctxa[nf][0] *= sc1; ctxa[nf][1] *= sc1;
            ctxa[nf][2] *= sc2; ctxa[nf][3] *= sc2;
        }

        // ctx += P @ V — flattened, ping-pong B fragments; P direct from registers
        {
            uint32_t bb[2][4];
            ldsm4(bb[0], sV + (uint32_t)(brow * FROW + bcol) * 2u);
            #pragma unroll
            for (int i = 0; i < 64; i++) {
                const int ks = i >> 3, p = i & 7, cur = i & 1;
                if (i < 63) {
                    const int nks = (i + 1) >> 3, np = (i + 1) & 7;
                    ldsm4(bb[cur ^ 1],
                          sV + (uint32_t)((np * 16 + brow) * FROW + nks * 16 + bcol) * 2u);
                }
                uint32_t afr[4] = { pA[2 * ks], pB[2 * ks], pA[2 * ks + 1], pB[2 * ks + 1] };
                mma16(ctxa[2 * p],     afr, bb[cur][0], bb[cur][1]);
                mma16(ctxa[2 * p + 1], afr, bb[cur][2], bb[cur][3]);
            }
        }
        // no trailing barrier: next iteration's top sync is the rendezvous
    }

    // epilogue: normalize, write fp16 ctx [b*s][h*d]
    float il1 = 1.f / l1, il2 = 1.f / l2;
    const int sr1 = qb * 128 + rl1, sr2 = qb * 128 + rl2;
    #pragma unroll
    for (int nf = 0; nf < 16; nf++) {
        int d0 = nf * 8 + 2 * qt;
        size_t o1 = ((size_t)(b * 1024 + sr1)) * 4096 + h * 128 + d0;
        size_t o2 = ((size_t)(b * 1024 + sr2)) * 4096 + h * 128 + d0;
        *(__half2*)(ctx + o1) = __floats2half2_rn(ctxa[nf][0] * il1, ctxa[nf][1] * il1);
        *(__half2*)(ctx + o2) = __floats2half2_rn(ctxa[nf][2] * il2, ctxa[nf][3] * il2);
    }
}

// -------- launch --------
extern "C" void kernel_launch(void* const* d_in, const int* in_sizes, int n_in,
                              void* d_out, int out_size) {
    const float* x    = (const float*)d_in[0];
    const float* mask = (const float*)d_in[1];
    const float* nw   = (const float*)d_in[2];
    const float* nb   = (const float*)d_in[3];
    const float* qkvw = (const float*)d_in[4];
    const float* qkvb = (const float*)d_in[5];
    const float* ow   = (const float*)d_in[6];
    float* out = (float*)d_out;

    __half *xn, *qv, *kv, *vv, *wbuf, *ctx;
    cudaGetSymbolAddress((void**)&xn,   g_xn);
    cudaGetSymbolAddress((void**)&qv,   g_q);
    cudaGetSymbolAddress((void**)&kv,   g_k);
    cudaGetSymbolAddress((void**)&vv,   g_v);
    cudaGetSymbolAddress((void**)&wbuf, g_w);
    cudaGetSymbolAddress((void**)&ctx,  g_ctx);
    __half* wT  = wbuf;               // [12288][4096]
    __half* owT = wbuf + 50331648;    // [4096][4096]

    const int GSMEM = 3 * GSTG;       // 110592 B -> 2 CTAs/SM
    const int FSMEM = 4 * FTILE + 4096;   // 143360 B
    cudaFuncSetAttribute(gemm_k<0>, cudaFuncAttributeMaxDynamicSharedMemorySize, GSMEM);
    cudaFuncSetAttribute(gemm_k<3>, cudaFuncAttributeMaxDynamicSharedMemorySize, GSMEM);
    cudaFuncSetAttribute(flash_k,   cudaFuncAttributeMaxDynamicSharedMemorySize, FSMEM);

    // weight prep: fp16 + transpose to [N][K]
    transpose_h<<<dim3(384, 128), 256>>>(qkvw, wT, 4096, 12288);
    transpose_h<<<dim3(128, 128), 256>>>(ow, owT, 4096, 4096);

    // layernorm (fp16 output)
    ln_kernel<<<MTOK, 256>>>(x, nw, nb, xn);

    // QKV GEMM + bias + scatter (q scaled, v transposed+coalesced)
    gemm_k<0><<<dim3(16, 96), 256, GSMEM>>>(xn, wT, nullptr, 12288, HID, qkvb, qv, kv, vv);

    // fused flash attention -> ctx
    flash_k<<<dim3(8, BHTOT), 256, FSMEM>>>(qv, kv, vv, mask, ctx);

    // output projection
    gemm_k<3><<<dim3(16, 32), 256, GSMEM>>>(ctx, owT, out, HID, HID, nullptr,
                                            nullptr, nullptr, nullptr);
}

// round 17
// speedup vs baseline: 1.0044x; 1.0044x over previous
#include <cuda_runtime.h>
#include <cuda_fp16.h>
#include <cstdint>
#include <math.h>

// Problem constants
#define HID   4096
#define NHEAD 32
#define HDIM  128
#define BATCH 2
#define SEQ   1024
#define MTOK  2048
#define BHTOT 64
#define QSCALE 0.08838834764831845f   // 1/sqrt(128)

// -------- scratch (__device__ globals; no allocation allowed) --------
__device__ __half g_xn [MTOK * HID];            // fp16 layernorm output
__device__ __half g_q  [BHTOT * SEQ * HDIM];    // [bh][s][d], pre-scaled
__device__ __half g_k  [BHTOT * SEQ * HDIM];    // [bh][s][d]
__device__ __half g_v  [BHTOT * SEQ * HDIM];    // [bh][d][s], TRANSPOSED
__device__ __half g_w  [67108864];              // qkv_w^T (50331648) + ow^T (16777216)
__device__ __half g_ctx[MTOK * HID];            // [b*s][h*d]

// -------- low-level helpers --------
__device__ __forceinline__ uint32_t sa(const void* p) {
    return (uint32_t)__cvta_generic_to_shared(p);
}
__device__ __forceinline__ void cp16(uint32_t s, const void* g) {
    asm volatile("cp.async.cg.shared.global [%0], [%1], 16;\n" :: "r"(s), "l"(g));
}
__device__ __forceinline__ void cp_commit() {
    asm volatile("cp.async.commit_group;\n");
}
template<int N>
__device__ __forceinline__ void cp_wait() {
    asm volatile("cp.async.wait_group %0;\n" :: "n"(N));
}
__device__ __forceinline__ void ldsm4(uint32_t r[4], uint32_t a) {
    asm volatile("ldmatrix.sync.aligned.m8n8.x4.shared.b16 {%0,%1,%2,%3}, [%4];"
        : "=r"(r[0]), "=r"(r[1]), "=r"(r[2]), "=r"(r[3]) : "r"(a));
}
// fp16 mma, fp32 accumulate: D(16x8) += A(16x16) @ B(16x8)
__device__ __forceinline__ void mma16(float c[4], const uint32_t a[4],
                                      uint32_t b0, uint32_t b1) {
    asm volatile(
        "mma.sync.aligned.m16n8k16.row.col.f32.f16.f16.f32 "
        "{%0,%1,%2,%3}, {%4,%5,%6,%7}, {%8,%9}, {%0,%1,%2,%3};"
        : "+f"(c[0]), "+f"(c[1]), "+f"(c[2]), "+f"(c[3])
        : "r"(a[0]), "r"(a[1]), "r"(a[2]), "r"(a[3]), "r"(b0), "r"(b1));
}

__device__ __forceinline__ float block_sum(float v) {
    __shared__ float sh[8];
    __syncthreads();
    #pragma unroll
    for (int o = 16; o; o >>= 1) v += __shfl_xor_sync(0xffffffffu, v, o);
    if ((threadIdx.x & 31) == 0) sh[threadIdx.x >> 5] = v;
    __syncthreads();
    v = sh[0];
    #pragma unroll
    for (int i = 1; i < 8; i++) v += sh[i];
    return v;
}

// -------- weight prep: transpose [R][C] -> [C][R], fp32 -> fp16 --------
__global__ void transpose_h(const float* __restrict__ in, __half* __restrict__ out,
                            int R, int C) {
    __shared__ float t[32][33];
    const int tx = threadIdx.x & 31, ty = threadIdx.x >> 5;
    const int c0 = blockIdx.x * 32, r0 = blockIdx.y * 32;
    #pragma unroll
    for (int i = 0; i < 4; i++)
        t[ty + i * 8][tx] = in[(size_t)(r0 + ty + i * 8) * C + c0 + tx];
    __syncthreads();
    #pragma unroll
    for (int i = 0; i < 4; i++)
        out[(size_t)(c0 + ty + i * 8) * R + r0 + tx] = __float2half_rn(t[tx][ty + i * 8]);
}

// -------- layernorm (fp16 output) --------
__global__ void ln_kernel(const float* __restrict__ x, const float* __restrict__ w,
                          const float* __restrict__ bb, __half* __restrict__ o) {
    size_t base = (size_t)blockIdx.x * HID;
    float4 vx[4];
    float s = 0.f, s2 = 0.f;
    #pragma unroll
    for (int i = 0; i < 4; i++) {
        vx[i] = *(const float4*)(x + base + (size_t)(threadIdx.x + i * 256) * 4);
        s  += vx[i].x + vx[i].y + vx[i].z + vx[i].w;
        s2 += vx[i].x * vx[i].x + vx[i].y * vx[i].y + vx[i].z * vx[i].z + vx[i].w * vx[i].w;
    }
    s  = block_sum(s);
    s2 = block_sum(s2);
    float mu  = s * (1.f / HID);
    float var = s2 * (1.f / HID) - mu * mu;
    float rs  = rsqrtf(var + 1e-5f);
    #pragma unroll
    for (int i = 0; i < 4; i++) {
        int c = (threadIdx.x + i * 256) * 4;
        float4 wv = *(const float4*)(w + c);
        float4 bv = *(const float4*)(bb + c);
        *(__half2*)(o + base + c)     = __floats2half2_rn((vx[i].x - mu) * rs * wv.x + bv.x,
                                                          (vx[i].y - mu) * rs * wv.y + bv.y);
        *(__half2*)(o + base + c + 2) = __floats2half2_rn((vx[i].z - mu) * rs * wv.z + bv.z,
                                                          (vx[i].w - mu) * rs * wv.w + bv.w);
    }
}

// -------- fp16 GEMM: C[M,N] = A[M,K] @ B[N,K]^T, 128x128x64, 256 thr, 2x4 warps --------
// R12-proven mainloop: 3-stage cp.async (wait_group 1), single barrier per slice,
// 2 CTAs/SM. MODE 0 v-tiles staged through smem for coalesced 16B stores.
// MODE 0: QKV epilogue (+bias, scatter q/k/v; q scaled; v transposed)
// MODE 3: plain fp32 store
#define GROW 72              // halves per smem row
#define GSTG 36864           // bytes per stage (A+B)

template<int MODE>
__device__ __forceinline__ void epi(int m, int n, float val, int N,
                                    const float* __restrict__ bias,
                                    float* __restrict__ out, __half* __restrict__ oq,
                                    __half* __restrict__ ok_) {
    if (MODE == 0) {
        val += bias[n];
        int which = n >> 12, nn = n & 4095;
        int h = nn >> 7, d = nn & 127, b = m >> 10, s = m & 1023;
        int bh = b * NHEAD + h;
        if (which == 0)      oq [((size_t)bh * 1024 + s) * 128 + d] = __float2half_rn(val * QSCALE);
        else                 ok_[((size_t)bh * 1024 + s) * 128 + d] = __float2half_rn(val);
    } else {
        out[(size_t)m * N + n] = val;
    }
}

template<int MODE>
__global__ void __launch_bounds__(256, 2) gemm_k(
    const __half* __restrict__ A, const __half* __restrict__ B, float* __restrict__ out,
    int N, int K, const float* __restrict__ bias,
    __half* __restrict__ oq, __half* __restrict__ ok_, __half* __restrict__ ov) {
    extern __shared__ __align__(16) char sm[];
    const int tid = threadIdx.x, lane = tid & 31, w = tid >> 5;
    const int wm = w & 1, wn = w >> 1, g = lane >> 2, qt = lane & 3;
    const int m0 = blockIdx.x * 128, n0 = blockIdx.y * 128;   // M fast axis
    const int KT = K / 64;
    const uint32_t smb = sa(sm);

    float acc[4][4][4];
    #pragma unroll
    for (int a = 0; a < 4; a++)
        #pragma unroll
        for (int b = 0; b < 4; b++)
            #pragma unroll
            for (int c = 0; c < 4; c++) acc[a][b][c] = 0.f;

    auto issue = [&](int kt, int st) {
        const uint32_t sA = smb + (uint32_t)st * GSTG;
        const uint32_t sB = sA + 128u * 144u;
        const int k0 = kt * 64;
        #pragma unroll
        for (int i = 0; i < 4; i++) {     // A: 128 rows x 8 chunks of 8 halves
            int id = tid + i * 256;
            int r = id >> 3, c = id & 7;
            cp16(sA + (uint32_t)(r * 144 + c * 16), A + (size_t)(m0 + r) * K + k0 + c * 8);
        }
        #pragma unroll
        for (int i = 0; i < 4; i++) {
            int id = tid + i * 256;
            int r = id >> 3, c = id & 7;
            cp16(sB + (uint32_t)(r * 144 + c * 16), B + (size_t)(n0 + r) * K + k0 + c * 8);
        }
    };

    issue(0, 0); cp_commit();
    issue(1, 1); cp_commit();

    // fragment lane addressing (halves)
    const int arow = wm * 64 + (lane & 7) + (lane & 8);   // + im*16
    const int acol = (lane >> 4) * 8;                     // + kb
    const int brow = (lane & 7) + (lane >> 4) * 8;        // + wn*32 + p*16
    const int bcol = ((lane >> 3) & 1) * 8;               // + kb

    int st_r = 0, st_w = 2;
    for (int kt = 0; kt < KT; kt++) {
        cp_wait<1>();
        __syncthreads();               // single barrier per slice
        if (kt + 2 < KT) issue(kt + 2, st_w);
        cp_commit();                   // commit every iter: group count exact
        if (++st_w == 3) st_w = 0;
        const uint32_t sA = smb + (uint32_t)st_r * GSTG;
        const uint32_t sB = sA + 128u * 144u;
        if (++st_r == 3) st_r = 0;
        #pragma unroll
        for (int ks = 0; ks < 4; ks++) {            // four k16 steps per 64-slice
            const int kb = ks * 16;
            uint32_t af[4][4], bf[2][4];
            #pragma unroll
            for (int im = 0; im < 4; im++)
                ldsm4(af[im], sA + (uint32_t)((arow + im * 16) * GROW + kb + acol) * 2u);
            #pragma unroll
            for (int p = 0; p < 2; p++)
                ldsm4(bf[p], sB + (uint32_t)((wn * 32 + p * 16 + brow) * GROW + kb + bcol) * 2u);
            #pragma unroll
            for (int im = 0; im < 4; im++)
                #pragma unroll
                for (int jn = 0; jn < 4; jn++)
                    mma16(acc[im][jn], af[im], bf[jn >> 1][(jn & 1) * 2],
                          bf[jn >> 1][(jn & 1) * 2 + 1]);
        }
    }

    if (MODE == 0 && n0 >= 8192) {
        // v-tile: stage through smem, then coalesced [d][s] stores.
        __syncthreads();               // stage buffers free
        __half* vs = (__half*)sm;      // [128][136] halves
        #pragma unroll
        for (int im = 0; im < 4; im++) {
            int ml = wm * 64 + im * 16 + g;
            #pragma unroll
            for (int jn = 0; jn < 4; jn++) {
                int nl = wn * 32 + jn * 8 + 2 * qt;
                vs[nl * 136 + ml]           = __float2half_rn(acc[im][jn][0] + bias[n0 + nl]);
                vs[(nl + 1) * 136 + ml]     = __float2half_rn(acc[im][jn][1] + bias[n0 + nl + 1]);
                vs[nl * 136 + ml + 8]       = __float2half_rn(acc[im][jn][2] + bias[n0 + nl]);
                vs[(nl + 1) * 136 + ml + 8] = __float2half_rn(acc[im][jn][3] + bias[n0 + nl + 1]);
            }
        }
        __syncthreads();
        const int b = m0 >> 10, h = (n0 & 4095) >> 7;
        const int bh = b * NHEAD + h, s0 = m0 & 1023;
        #pragma unroll
        for (int i = 0; i < 8; i++) {    // 128 rows x 16 chunks of 16B
            int u = tid + i * 256;
            int r = u >> 4, c = u & 15;
            *(uint4*)(ov + (size_t)(bh * 128 + r) * 1024 + s0 + c * 8) =
                *(uint4*)(vs + r * 136 + c * 8);
        }
    } else {
        #pragma unroll
        for (int im = 0; im < 4; im++) {
            int mr = m0 + wm * 64 + im * 16 + g;
            #pragma unroll
            for (int jn = 0; jn < 4; jn++) {
                int nc = n0 + wn * 32 + jn * 8 + 2 * qt;
                epi<MODE>(mr,     nc,     acc[im][jn][0], N, bias, out, oq, ok_);
                epi<MODE>(mr,     nc + 1, acc[im][jn][1], N, bias, out, oq, ok_);
                epi<MODE>(mr + 8, nc,     acc[im][jn][2], N, bias, out, oq, ok_);
                epi<MODE>(mr + 8, nc + 1, acc[im][jn][3], N, bias, out, oq, ok_);
            }
        }
    }
}

// -------- fp16 flash attention: P in regs, KV double-buffered, 1 barrier/j --------
// per CTA one (bh, 128-row q block); 8 warps x 16 rows.
// smem: K0,K1,V0,V1 (4 x 34816B) + mask (4KB) = 143360B, occ 1.
#define FROW 136
#define FTILE 34816
#define MOFF  (4 * FTILE)

__global__ void __launch_bounds__(256, 1) flash_k(
    const __half* __restrict__ q, const __half* __restrict__ k, const __half* __restrict__ v,
    const float* __restrict__ mask, __half* __restrict__ ctx) {
    extern __shared__ __align__(16) char sm[];
    const int tid = threadIdx.x, lane = tid & 31, w = tid >> 5;
    const int g = lane >> 2, qt = lane & 3;
    const int qb = (int)(gridDim.x - 1) - (int)blockIdx.x;   // heavy CTAs first
    const int bh = blockIdx.y, b = bh >> 5, h = bh & 31;
    const size_t hoff = (size_t)bh * 131072;
    const uint32_t smb = sa(sm);
    float* smf = (float*)(sm + MOFF);

    const int arow = w * 16 + (lane & 7) + (lane & 8);
    const int acol = (lane >> 4) * 8;
    const int brow = (lane & 7) + (lane >> 4) * 8;
    const int bcol = ((lane >> 3) & 1) * 8;

    auto issue_KV = [&](int j, int buf) {
        const uint32_t sK = smb + (uint32_t)buf * FTILE;
        const uint32_t sV = smb + (uint32_t)(2 + buf) * FTILE;
        #pragma unroll
        for (int i = 0; i < 8; i++) {
            int id = tid + i * 256;
            int r = id >> 4, c = id & 15;
            cp16(sK + (uint32_t)(r * 272 + c * 16), k + hoff + (size_t)(j * 128 + r) * 128 + c * 8);
        }
        #pragma unroll
        for (int i = 0; i < 8; i++) {
            int id = tid + i * 256;
            int r = id >> 4, c = id & 15;
            cp16(sV + (uint32_t)(r * 272 + c * 16), v + hoff + (size_t)r * 1024 + j * 128 + c * 8);
        }
    };

    // mask row -> smem (1024 floats)
    *((float4*)smf + tid) = *((const float4*)(mask + b * 1024) + tid);

    // stage Q through K-buffer 0, pull fragments into registers
    {
        const uint32_t sK0 = smb;
        #pragma unroll
        for (int i = 0; i < 8; i++) {
            int id = tid + i * 256;
            int r = id >> 4, c = id & 15;
            cp16(sK0 + (uint32_t)(r * 272 + c * 16), q + hoff + (size_t)(qb * 128 + r) * 128 + c * 8);
        }
        cp_commit(); cp_wait<0>();
    }
    __syncthreads();
    uint32_t qf[8][4];
    #pragma unroll
    for (int kf = 0; kf < 8; kf++)
        ldsm4(qf[kf], smb + (uint32_t)(arow * FROW + kf * 16 + acol) * 2u);
    __syncthreads();           // qf reads done before KV(0) overwrites buffer 0

    issue_KV(0, 0); cp_commit();

    float ctxa[16][4];
    #pragma unroll
    for (int i = 0; i < 16; i++) { ctxa[i][0] = ctxa[i][1] = ctxa[i][2] = ctxa[i][3] = 0.f; }
    float m1 = -1e30f, m2 = -1e30f, l1 = 0.f, l2 = 0.f;
    const int rl1 = w * 16 + g, rl2 = rl1 + 8;

    for (int j = 0; j <= qb; j++) {
        const int buf = j & 1;
        const uint32_t sK = smb + (uint32_t)buf * FTILE;
        const uint32_t sV = smb + (uint32_t)(2 + buf) * FTILE;
        cp_wait<0>();
        __syncthreads();       // KV(j) visible; all warps past PV(j-1)
        if (j < qb) { issue_KV(j + 1, buf ^ 1); cp_commit(); }

        // S = Q @ K^T — flattened (ks,p) loop, ping-pong B fragments
        float sacc[16][4];
        #pragma unroll
        for (int i = 0; i < 16; i++) { sacc[i][0] = sacc[i][1] = sacc[i][2] = sacc[i][3] = 0.f; }
        {
            uint32_t bb[2][4];
            ldsm4(bb[0], sK + (uint32_t)(brow * FROW + bcol) * 2u);
            #pragma unroll
            for (int i = 0; i < 64; i++) {
                const int ks = i >> 3, p = i & 7, cur = i & 1;
                if (i < 63) {
                    const int nks = (i + 1) >> 3, np = (i + 1) & 7;
                    ldsm4(bb[cur ^ 1],
                          sK + (uint32_t)((np * 16 + brow) * FROW + nks * 16 + bcol) * 2u);
                }
                mma16(sacc[2 * p],     qf[ks], bb[cur][0], bb[cur][1]);
                mma16(sacc[2 * p + 1], qf[ks], bb[cur][2], bb[cur][3]);
            }
        }

        // online softmax (row stats warp-local; lanes 4g..4g+3 share rows)
        const bool diag = (j == qb);
        float mx1 = -1e30f, mx2 = -1e30f;
        #pragma unroll
        for (int nf = 0; nf < 16; nf++) {
            int c0 = nf * 8 + 2 * qt, cg = j * 128 + c0;
            float mk0 = smf[cg], mk1 = smf[cg + 1];
            float s0 = sacc[nf][0] + mk0, s1 = sacc[nf][1] + mk1;
            float s2 = sacc[nf][2] + mk0, s3 = sacc[nf][3] + mk1;
            if (diag) {
                if (c0     > rl1) s0 = -1e30f;
                if (c0 + 1 > rl1) s1 = -1e30f;
                if (c0     > rl2) s2 = -1e30f;
                if (c0 + 1 > rl2) s3 = -1e30f;
            }
            sacc[nf][0] = s0; sacc[nf][1] = s1; sacc[nf][2] = s2; sacc[nf][3] = s3;
            mx1 = fmaxf(mx1, fmaxf(s0, s1));
            mx2 = fmaxf(mx2, fmaxf(s2, s3));
        }
        #pragma unroll
        for (int o = 1; o < 4; o <<= 1) {
            mx1 = fmaxf(mx1, __shfl_xor_sync(0xffffffffu, mx1, o));
            mx2 = fmaxf(mx2, __shfl_xor_sync(0xffffffffu, mx2, o));
        }
        float mn1 = fmaxf(m1, mx1), mn2 = fmaxf(m2, mx2);
        float sc1 = __expf(m1 - mn1), sc2 = __expf(m2 - mn2);
        float su1 = 0.f, su2 = 0.f;
        uint32_t pA[16], pB[16];       // P as mma A-fragments (rows g / g+8)
        #pragma unroll
        for (int nf = 0; nf < 16; nf++) {
            float p0 = __expf(sacc[nf][0] - mn1), p1 = __expf(sacc[nf][1] - mn1);
            float p2 = __expf(sacc[nf][2] - mn2), p3 = __expf(sacc[nf][3] - mn2);
            su1 += p0 + p1;
            su2 += p2 + p3;
            __half2 h01 = __floats2half2_rn(p0, p1);
            __half2 h23 = __floats2half2_rn(p2, p3);
            pA[nf] = *reinterpret_cast<uint32_t*>(&h01);
            pB[nf] = *reinterpret_cast<uint32_t*>(&h23);
        }
        #pragma unroll
        for (int o = 1; o < 4; o <<= 1) {
            su1 += __shfl_xor_sync(0xffffffffu, su1, o);
            su2 += __shfl_xor_sync(0xffffffffu, su2, o);
        }
        l1 = l1 * sc1 + su1;
        l2 = l2 * sc2 + su2;
        m1 = mn1; m2 = mn2;
        #pragma unroll
        for (int nf = 0; nf < 16; nf++) {
            ctxa[nf][0] *= sc1; ctxa[nf][1] *= sc1;
            ctxa[nf][2] *= sc2; ctxa[nf][3] *= sc2;
        }

        // ctx += P @ V — flattened, ping-pong B fragments; P direct from registers
        {
            uint32_t bb[2][4];
            ldsm4(bb[0], sV + (uint32_t)(brow * FROW + bcol) * 2u);
            #pragma unroll
            for (int i = 0; i < 64; i++) {
                const int ks = i >> 3, p = i & 7, cur = i & 1;
                if (i < 63) {
                    const int nks = (i + 1) >> 3, np = (i + 1) & 7;
                    ldsm4(bb[cur ^ 1],
                          sV + (uint32_t)((np * 16 + brow) * FROW + nks * 16 + bcol) * 2u);
                }
                uint32_t afr[4] = { pA[2 * ks], pB[2 * ks], pA[2 * ks + 1], pB[2 * ks + 1] };
                mma16(ctxa[2 * p],     afr, bb[cur][0], bb[cur][1]);
                mma16(ctxa[2 * p + 1], afr, bb[cur][2], bb[cur][3]);
            }
        }
        // no trailing barrier: next iteration's top sync is the rendezvous
    }

    // epilogue: normalize, write fp16 ctx [b*s][h*d]
    float il1 = 1.f / l1, il2 = 1.f / l2;
    const int sr1 = qb * 128 + rl1, sr2 = qb * 128 + rl2;
    #pragma unroll
    for (int nf = 0; nf < 16; nf++) {
        int d0 = nf * 8 + 2 * qt;
        size_t o1 = ((size_t)(b * 1024 + sr1)) * 4096 + h * 128 + d0;
        size_t o2 = ((size_t)(b * 1024 + sr2)) * 4096 + h * 128 + d0;
        *(__half2*)(ctx + o1) = __floats2half2_rn(ctxa[nf][0] * il1, ctxa[nf][1] * il1);
        *(__half2*)(ctx + o2) = __floats2half2_rn(ctxa[nf][2] * il2, ctxa[nf][3] * il2);
    }
}

// -------- launch: fork-join DAG (graph-capturable event pattern) --------
// s1: transpose(qkvw)  — joins before gemm0
// s2: transpose(ow)    — joins before proj (hidden under gemm0+flash)
// main: LN -> gemm0 -> flash -> proj
extern "C" void kernel_launch(void* const* d_in, const int* in_sizes, int n_in,
                              void* d_out, int out_size) {
    const float* x    = (const float*)d_in[0];
    const float* mask = (const float*)d_in[1];
    const float* nw   = (const float*)d_in[2];
    const float* nb   = (const float*)d_in[3];
    const float* qkvw = (const float*)d_in[4];
    const float* qkvb = (const float*)d_in[5];
    const float* ow   = (const float*)d_in[6];
    float* out = (float*)d_out;

    __half *xn, *qv, *kv, *vv, *wbuf, *ctx;
    cudaGetSymbolAddress((void**)&xn,   g_xn);
    cudaGetSymbolAddress((void**)&qv,   g_q);
    cudaGetSymbolAddress((void**)&kv,   g_k);
    cudaGetSymbolAddress((void**)&vv,   g_v);
    cudaGetSymbolAddress((void**)&wbuf, g_w);
    cudaGetSymbolAddress((void**)&ctx,  g_ctx);
    __half* wT  = wbuf;               // [12288][4096]
    __half* owT = wbuf + 50331648;    // [4096][4096]

    const int GSMEM = 3 * GSTG;       // 110592 B -> 2 CTAs/SM
    const int FSMEM = 4 * FTILE + 4096;   // 143360 B
    cudaFuncSetAttribute(gemm_k<0>, cudaFuncAttributeMaxDynamicSharedMemorySize, GSMEM);
    cudaFuncSetAttribute(gemm_k<3>, cudaFuncAttributeMaxDynamicSharedMemorySize, GSMEM);
    cudaFuncSetAttribute(flash_k,   cudaFuncAttributeMaxDynamicSharedMemorySize, FSMEM);

    // one-time host resources (no device memory involved)
    static cudaStream_t s1 = nullptr, s2 = nullptr;
    static cudaEvent_t ef = nullptr, e1 = nullptr, e2 = nullptr;
    if (s1 == nullptr) {
        cudaStreamCreateWithFlags(&s1, cudaStreamNonBlocking);
        cudaStreamCreateWithFlags(&s2, cudaStreamNonBlocking);
        cudaEventCreateWithFlags(&ef, cudaEventDisableTiming);
        cudaEventCreateWithFlags(&e1, cudaEventDisableTiming);
        cudaEventCreateWithFlags(&e2, cudaEventDisableTiming);
    }

    // fork
    cudaEventRecord(ef, 0);
    cudaStreamWaitEvent(s1, ef, 0);
    cudaStreamWaitEvent(s2, ef, 0);

    // side stream 1: qkv_w prep (needed by gemm0)
    transpose_h<<<dim3(384, 128), 256, 0, s1>>>(qkvw, wT, 4096, 12288);
    cudaEventRecord(e1, s1);

    // side stream 2: ow prep (needed only by proj)
    transpose_h<<<dim3(128, 128), 256, 0, s2>>>(ow, owT, 4096, 4096);
    cudaEventRecord(e2, s2);

    // main stream: LN in parallel with prep
    ln_kernel<<<MTOK, 256>>>(x, nw, nb, xn);

    // join wT before QKV GEMM
    cudaStreamWaitEvent(0, e1, 0);
    gemm_k<0><<<dim3(16, 96), 256, GSMEM>>>(xn, wT, nullptr, 12288, HID, qkvb, qv, kv, vv);

    // fused flash attention -> ctx
    flash_k<<<dim3(8, BHTOT), 256, FSMEM>>>(qv, kv, vv, mask, ctx);

    // join owT before output projection
    cudaStreamWaitEvent(0, e2, 0);
    gemm_k<3><<<dim3(16, 32), 256, GSMEM>>>(ctx, owT, out, HID, HID, nullptr,
                                            nullptr, nullptr, nullptr);
}